// round 2
// baseline (speedup 1.0000x reference)
#include <cuda_runtime.h>
#include <math.h>

#define NN 50000
#define MAXE 1600000
#define H 128
#define CC 40
#define EPS 1e-5f

// ---------------- static device scratch (no allocations allowed) ----------------
__device__ float g_buf0[NN * H];        // ping
__device__ float g_buf1[NN * H];        // pong
__device__ float g_deg[NN];
__device__ float g_dis[NN];
__device__ float g_sn[NN];              // dis^2 (self-loop norm)
__device__ float g_norm[MAXE];
__device__ float g_sum[H];
__device__ float g_sumsq[H];
__device__ float g_scale[H];
__device__ float g_shift[H];
__device__ float g_logits_scratch[NN * CC];

// ---------------- preamble kernels ----------------
__global__ void k_deg_init(float* __restrict__ deg, int n) {
    int i = blockIdx.x * blockDim.x + threadIdx.x;
    if (i < n) deg[i] = 1.0f;  // self loop
}

__global__ void k_deg_acc(const int* __restrict__ dst, float* __restrict__ deg, int e) {
    int i = blockIdx.x * blockDim.x + threadIdx.x;
    if (i < e) atomicAdd(&deg[dst[i]], 1.0f);
}

__global__ void k_dis(const float* __restrict__ deg, float* __restrict__ dis,
                      float* __restrict__ sn, int n) {
    int i = blockIdx.x * blockDim.x + threadIdx.x;
    if (i < n) {
        float d = rsqrtf(deg[i]);   // deg >= 1 always
        dis[i] = d;
        sn[i] = d * d;
    }
}

__global__ void k_norm(const int* __restrict__ src, const int* __restrict__ dst,
                       const float* __restrict__ dis, float* __restrict__ norm, int e) {
    int i = blockIdx.x * blockDim.x + threadIdx.x;
    if (i < e) norm[i] = __ldg(&dis[src[i]]) * __ldg(&dis[dst[i]]);
}

// ---------------- GEMM: C[n,128] = f(A)[n,128] @ W[128,128] ----------------
// f(A) = A if scale==null, else relu(A*scale[col] + shift[col])  (fused BN+ReLU)
__global__ __launch_bounds__(256)
void k_gemm(const float* __restrict__ A, const float* __restrict__ W,
            const float* __restrict__ scale, const float* __restrict__ shift,
            float* __restrict__ Cout, int n) {
    __shared__ float As[128 * 33];   // 128 rows x 32 k-chunk, padded
    __shared__ float Ws[32 * 128];   // 32 k x 128 cols

    int tid = threadIdx.x;
    int tx = tid & 15;               // 0..15 -> col group *8
    int ty = tid >> 4;               // 0..15 -> row group *8
    int row0 = blockIdx.x * 128;

    float acc[8][8];
#pragma unroll
    for (int i = 0; i < 8; i++)
#pragma unroll
        for (int j = 0; j < 8; j++) acc[i][j] = 0.0f;

    for (int k0 = 0; k0 < 128; k0 += 32) {
        // load A chunk with fused affine+relu
        for (int i = tid; i < 128 * 32; i += 256) {
            int r = i >> 5, c = i & 31;
            int gr = row0 + r;
            float v = 0.0f;
            if (gr < n) {
                v = A[(size_t)gr * 128 + k0 + c];
                if (scale) v = fmaxf(v * scale[k0 + c] + shift[k0 + c], 0.0f);
            }
            As[r * 33 + c] = v;
        }
        // load W chunk
        for (int i = tid; i < 32 * 128; i += 256) {
            int kk = i >> 7, nn = i & 127;
            Ws[i] = W[(size_t)(k0 + kk) * 128 + nn];
        }
        __syncthreads();

#pragma unroll
        for (int kk = 0; kk < 32; kk++) {
            float a[8];
#pragma unroll
            for (int i = 0; i < 8; i++) a[i] = As[(ty * 8 + i) * 33 + kk];
            float4 w0 = *(const float4*)&Ws[kk * 128 + tx * 8];
            float4 w1 = *(const float4*)&Ws[kk * 128 + tx * 8 + 4];
#pragma unroll
            for (int i = 0; i < 8; i++) {
                acc[i][0] += a[i] * w0.x;
                acc[i][1] += a[i] * w0.y;
                acc[i][2] += a[i] * w0.z;
                acc[i][3] += a[i] * w0.w;
                acc[i][4] += a[i] * w1.x;
                acc[i][5] += a[i] * w1.y;
                acc[i][6] += a[i] * w1.z;
                acc[i][7] += a[i] * w1.w;
            }
        }
        __syncthreads();
    }

#pragma unroll
    for (int i = 0; i < 8; i++) {
        int gr = row0 + ty * 8 + i;
        if (gr < n) {
            float4* p = (float4*)&Cout[(size_t)gr * 128 + tx * 8];
            p[0] = make_float4(acc[i][0], acc[i][1], acc[i][2], acc[i][3]);
            p[1] = make_float4(acc[i][4], acc[i][5], acc[i][6], acc[i][7]);
        }
    }
}

// ---------------- agg init: agg = b + hw * selfnorm ----------------
__global__ void k_agg_init(const float* __restrict__ hw, const float* __restrict__ bias,
                           const float* __restrict__ sn, float* __restrict__ agg, int n) {
    int i = blockIdx.x * blockDim.x + threadIdx.x;   // over n*32 float4s
    if (i >= n * 32) return;
    int node = i >> 5, lane = i & 31;
    float s = sn[node];
    float4 v = ((const float4*)hw)[i];
    float4 b = ((const float4*)bias)[lane];
    float4 o;
    o.x = b.x + v.x * s;
    o.y = b.y + v.y * s;
    o.z = b.z + v.z * s;
    o.w = b.w + v.w * s;
    ((float4*)agg)[i] = o;
}

// ---------------- edge scatter: one warp per edge, red.v4.f32 ----------------
__global__ void k_scatter(const float* __restrict__ hw, const int* __restrict__ src,
                          const int* __restrict__ dst, const float* __restrict__ norm,
                          float* __restrict__ agg, int e) {
    int g = blockIdx.x * blockDim.x + threadIdx.x;
    int edge = g >> 5, lane = g & 31;
    if (edge >= e) return;
    int s = __ldg(&src[edge]);
    int d = __ldg(&dst[edge]);
    float w = __ldg(&norm[edge]);
    float4 v = ((const float4*)hw)[(size_t)s * 32 + lane];
    float4* out = ((float4*)agg) + (size_t)d * 32 + lane;
    asm volatile("red.global.add.v4.f32 [%0], {%1, %2, %3, %4};"
                 :: "l"(out), "f"(v.x * w), "f"(v.y * w), "f"(v.z * w), "f"(v.w * w)
                 : "memory");
}

// ---------------- BN stats ----------------
__global__ void k_zero_stats(float* __restrict__ sum, float* __restrict__ sumsq) {
    int c = threadIdx.x;
    if (c < H) { sum[c] = 0.0f; sumsq[c] = 0.0f; }
}

__global__ void k_bn_stats(const float* __restrict__ agg, float* __restrict__ sum,
                           float* __restrict__ sumsq, int n) {
    int c = threadIdx.x;  // 128 threads
    float s = 0.0f, sq = 0.0f;
    for (int r = blockIdx.x; r < n; r += gridDim.x) {
        float v = agg[(size_t)r * 128 + c];
        s += v;
        sq += v * v;
    }
    atomicAdd(&sum[c], s);
    atomicAdd(&sumsq[c], sq);
}

__global__ void k_bn_fin(const float* __restrict__ gamma, const float* __restrict__ beta,
                         const float* __restrict__ sum, const float* __restrict__ sumsq,
                         float* __restrict__ scale, float* __restrict__ shift, int n) {
    int c = threadIdx.x;
    if (c >= H) return;
    float inv_n = 1.0f / (float)n;
    float mean = sum[c] * inv_n;
    float var = fmaxf(sumsq[c] * inv_n - mean * mean, 0.0f);
    float inv = rsqrtf(var + EPS);
    float sc = gamma[c] * inv;
    scale[c] = sc;
    shift[c] = beta[c] - mean * sc;
}

// ---------------- head: BN3+ReLU -> FC -> ReLU -> log_softmax ----------------
__global__ __launch_bounds__(256)
void k_head(const float* __restrict__ agg, const float* __restrict__ fcW,
            const float* __restrict__ fcb, const float* __restrict__ scale,
            const float* __restrict__ shift, float* __restrict__ lsm,
            float* __restrict__ logits, int n) {
    __shared__ float Wf[128 * 40];
    __shared__ float fb[40];
    __shared__ float hs[32][129];
    __shared__ float lg[32][40];
    __shared__ float nlse[32];

    int tid = threadIdx.x;
    for (int i = tid; i < 128 * 40; i += 256) Wf[i] = fcW[i];
    if (tid < 40) fb[tid] = fcb[tid];

    int node0 = blockIdx.x * 32;
    for (int i = tid; i < 32 * 128; i += 256) {
        int r = i >> 7, c = i & 127;
        int gn = node0 + r;
        float v = 0.0f;
        if (gn < n) {
            v = agg[(size_t)gn * 128 + c];
            v = fmaxf(v * scale[c] + shift[c], 0.0f);
        }
        hs[r][c] = v;
    }
    __syncthreads();

    // 8 threads per node, 5 classes each
    int nd = tid >> 3;
    int cg = (tid & 7) * 5;
    float acc[5] = {0, 0, 0, 0, 0};
    for (int k = 0; k < 128; k++) {
        float h = hs[nd][k];
#pragma unroll
        for (int j = 0; j < 5; j++) acc[j] += h * Wf[k * 40 + cg + j];
    }
#pragma unroll
    for (int j = 0; j < 5; j++) lg[nd][cg + j] = fmaxf(acc[j] + fb[cg + j], 0.0f);
    __syncthreads();

    if (tid < 32) {
        float m = -1e30f;
        for (int c = 0; c < 40; c++) m = fmaxf(m, lg[tid][c]);
        float s = 0.0f;
        for (int c = 0; c < 40; c++) s += expf(lg[tid][c] - m);
        nlse[tid] = m + logf(s);
    }
    __syncthreads();

    for (int i = tid; i < 32 * 40; i += 256) {
        int r = i / 40, c = i - r * 40;
        int gn = node0 + r;
        if (gn < n) {
            float l = lg[r][c];
            logits[(size_t)gn * 40 + c] = l;
            lsm[(size_t)gn * 40 + c] = l - nlse[r];
        }
    }
}

// ---------------- host ----------------
extern "C" void kernel_launch(void* const* d_in, const int* in_sizes, int n_in,
                              void* d_out, int out_size) {
    const float* x   = (const float*)d_in[0];
    const int*   ei  = (const int*)d_in[1];
    const float* W1  = (const float*)d_in[2];
    const float* b1  = (const float*)d_in[3];
    const float* W2  = (const float*)d_in[4];
    const float* b2  = (const float*)d_in[5];
    const float* W3  = (const float*)d_in[6];
    const float* b3  = (const float*)d_in[7];
    const float* g1  = (const float*)d_in[8];
    const float* be1 = (const float*)d_in[9];
    const float* g2  = (const float*)d_in[10];
    const float* be2 = (const float*)d_in[11];
    const float* g3  = (const float*)d_in[12];
    const float* be3 = (const float*)d_in[13];
    const float* fcW = (const float*)d_in[14];
    const float* fcb = (const float*)d_in[15];

    int n = in_sizes[0] / H;
    int e = in_sizes[1] / 2;
    const int* src = ei;
    const int* dst = ei + e;

    float *buf0, *buf1, *deg, *dis, *sn, *norm, *sum, *sumsq, *scale, *shift, *lsc;
    cudaGetSymbolAddress((void**)&buf0, g_buf0);
    cudaGetSymbolAddress((void**)&buf1, g_buf1);
    cudaGetSymbolAddress((void**)&deg, g_deg);
    cudaGetSymbolAddress((void**)&dis, g_dis);
    cudaGetSymbolAddress((void**)&sn, g_sn);
    cudaGetSymbolAddress((void**)&norm, g_norm);
    cudaGetSymbolAddress((void**)&sum, g_sum);
    cudaGetSymbolAddress((void**)&sumsq, g_sumsq);
    cudaGetSymbolAddress((void**)&scale, g_scale);
    cudaGetSymbolAddress((void**)&shift, g_shift);
    cudaGetSymbolAddress((void**)&lsc, g_logits_scratch);

    float* lsm = (float*)d_out;
    float* logits = (out_size >= 2 * n * CC) ? (lsm + (size_t)n * CC) : lsc;

    int nb = (n + 255) / 256;
    int ebks = (e + 255) / 256;
    int gemm_blocks = (n + 127) / 128;
    int agg_blocks = (n * 32 + 255) / 256;
    long long sc_threads = (long long)e * 32;
    int sc_blocks = (int)((sc_threads + 255) / 256);

    // preamble
    k_deg_init<<<nb, 256>>>(deg, n);
    k_deg_acc<<<ebks, 256>>>(dst, deg, e);
    k_dis<<<nb, 256>>>(deg, dis, sn, n);
    k_norm<<<ebks, 256>>>(src, dst, dis, norm, e);

    // ---- layer 1 ----
    k_gemm<<<gemm_blocks, 256>>>(x, W1, nullptr, nullptr, buf0, n);
    k_agg_init<<<agg_blocks, 256>>>(buf0, b1, sn, buf1, n);
    k_scatter<<<sc_blocks, 256>>>(buf0, src, dst, norm, buf1, e);
    k_zero_stats<<<1, 128>>>(sum, sumsq);
    k_bn_stats<<<256, 128>>>(buf1, sum, sumsq, n);
    k_bn_fin<<<1, 128>>>(g1, be1, sum, sumsq, scale, shift, n);

    // ---- layer 2 ----
    k_gemm<<<gemm_blocks, 256>>>(buf1, W2, scale, shift, buf0, n);
    k_agg_init<<<agg_blocks, 256>>>(buf0, b2, sn, buf1, n);
    k_scatter<<<sc_blocks, 256>>>(buf0, src, dst, norm, buf1, e);
    k_zero_stats<<<1, 128>>>(sum, sumsq);
    k_bn_stats<<<256, 128>>>(buf1, sum, sumsq, n);
    k_bn_fin<<<1, 128>>>(g2, be2, sum, sumsq, scale, shift, n);

    // ---- layer 3 ----
    k_gemm<<<gemm_blocks, 256>>>(buf1, W3, scale, shift, buf0, n);
    k_agg_init<<<agg_blocks, 256>>>(buf0, b3, sn, buf1, n);
    k_scatter<<<sc_blocks, 256>>>(buf0, src, dst, norm, buf1, e);
    k_zero_stats<<<1, 128>>>(sum, sumsq);
    k_bn_stats<<<256, 128>>>(buf1, sum, sumsq, n);
    k_bn_fin<<<1, 128>>>(g3, be3, sum, sumsq, scale, shift, n);

    // ---- head ----
    k_head<<<(n + 31) / 32, 256>>>(buf1, fcW, fcb, scale, shift, lsm, logits, n);
}

// round 3
// speedup vs baseline: 1.5793x; 1.5793x over previous
#include <cuda_runtime.h>
#include <math.h>

#define NN 50000
#define MAXE 1600000
#define H 128
#define CC 40
#define EPS 1e-5f

// ---------------- static device scratch ----------------
__device__ float g_buf0[NN * H];
__device__ float g_buf1[NN * H];
__device__ float g_dis[NN];
__device__ int   g_cnt[NN];          // in-degree (no self loop)
__device__ int   g_rowptr[NN + 1];
__device__ int   g_cursor[NN];
__device__ int   g_csrc[MAXE];       // CSR: src node per edge slot
__device__ float g_cw[MAXE];         // CSR: edge weight (norm)
__device__ float g_sum[H];
__device__ float g_sumsq[H];
__device__ float g_scale[H];
__device__ float g_shift[H];
__device__ float g_logits_scratch[NN * CC];

// ---------------- CSR build ----------------
__global__ void k_zero_cnt(int* __restrict__ cnt, int n) {
    int i = blockIdx.x * blockDim.x + threadIdx.x;
    if (i < n) cnt[i] = 0;
}

__global__ void k_count(const int* __restrict__ dst, int* __restrict__ cnt, int e) {
    int i = blockIdx.x * blockDim.x + threadIdx.x;
    if (i < e) atomicAdd(&cnt[dst[i]], 1);
}

__global__ void k_dis(const int* __restrict__ cnt, float* __restrict__ dis, int n) {
    int i = blockIdx.x * blockDim.x + threadIdx.x;
    if (i < n) dis[i] = rsqrtf((float)(cnt[i] + 1));   // deg includes self loop
}

// single-block chunked exclusive scan over n counts -> rowptr, cursor
__global__ void k_scan(const int* __restrict__ cnt, int* __restrict__ rowptr,
                       int* __restrict__ cursor, int n) {
    __shared__ int carry;
    __shared__ int warpsums[32];
    int tid = threadIdx.x;
    int lane = tid & 31, wid = tid >> 5;
    if (tid == 0) carry = 0;
    __syncthreads();
    for (int base = 0; base < n; base += 1024) {
        int i = base + tid;
        int v = (i < n) ? cnt[i] : 0;
        int x = v;
#pragma unroll
        for (int o = 1; o < 32; o <<= 1) {
            int t = __shfl_up_sync(0xffffffffu, x, o);
            if (lane >= o) x += t;
        }
        if (lane == 31) warpsums[wid] = x;
        __syncthreads();
        if (wid == 0) {
            int w = warpsums[lane];
#pragma unroll
            for (int o = 1; o < 32; o <<= 1) {
                int t = __shfl_up_sync(0xffffffffu, w, o);
                if (lane >= o) w += t;
            }
            warpsums[lane] = w;
        }
        __syncthreads();
        int excl = x - v + (wid > 0 ? warpsums[wid - 1] : 0) + carry;
        if (i < n) { rowptr[i] = excl; cursor[i] = excl; }
        __syncthreads();
        if (tid == 1023) carry = excl + v;
        __syncthreads();
    }
    if (tid == 0) rowptr[n] = carry;
}

__global__ void k_fill(const int* __restrict__ src, const int* __restrict__ dst,
                       const float* __restrict__ dis, int* __restrict__ cursor,
                       int* __restrict__ csrc, float* __restrict__ cw, int e) {
    int i = blockIdx.x * blockDim.x + threadIdx.x;
    if (i >= e) return;
    int s = src[i], d = dst[i];
    int pos = atomicAdd(&cursor[d], 1);
    csrc[pos] = s;
    cw[pos] = __ldg(&dis[s]) * __ldg(&dis[d]);
}

// ---------------- GEMM: C[n,128] = f(A)[n,128] @ W[128,128] ----------------
__global__ __launch_bounds__(256)
void k_gemm(const float* __restrict__ A, const float* __restrict__ W,
            const float* __restrict__ scale, const float* __restrict__ shift,
            float* __restrict__ Cout, int n) {
    __shared__ float As[128 * 33];
    __shared__ float Ws[32 * 128];

    int tid = threadIdx.x;
    int tx = tid & 15;
    int ty = tid >> 4;
    int row0 = blockIdx.x * 128;

    float acc[8][8];
#pragma unroll
    for (int i = 0; i < 8; i++)
#pragma unroll
        for (int j = 0; j < 8; j++) acc[i][j] = 0.0f;

    for (int k0 = 0; k0 < 128; k0 += 32) {
        for (int i = tid; i < 128 * 32; i += 256) {
            int r = i >> 5, c = i & 31;
            int gr = row0 + r;
            float v = 0.0f;
            if (gr < n) {
                v = A[(size_t)gr * 128 + k0 + c];
                if (scale) v = fmaxf(v * scale[k0 + c] + shift[k0 + c], 0.0f);
            }
            As[r * 33 + c] = v;
        }
        for (int i = tid; i < 32 * 128; i += 256) {
            int kk = i >> 7, nn = i & 127;
            Ws[i] = W[(size_t)(k0 + kk) * 128 + nn];
        }
        __syncthreads();

#pragma unroll
        for (int kk = 0; kk < 32; kk++) {
            float a[8];
#pragma unroll
            for (int i = 0; i < 8; i++) a[i] = As[(ty * 8 + i) * 33 + kk];
            float4 w0 = *(const float4*)&Ws[kk * 128 + tx * 8];
            float4 w1 = *(const float4*)&Ws[kk * 128 + tx * 8 + 4];
#pragma unroll
            for (int i = 0; i < 8; i++) {
                acc[i][0] += a[i] * w0.x;
                acc[i][1] += a[i] * w0.y;
                acc[i][2] += a[i] * w0.z;
                acc[i][3] += a[i] * w0.w;
                acc[i][4] += a[i] * w1.x;
                acc[i][5] += a[i] * w1.y;
                acc[i][6] += a[i] * w1.z;
                acc[i][7] += a[i] * w1.w;
            }
        }
        __syncthreads();
    }

#pragma unroll
    for (int i = 0; i < 8; i++) {
        int gr = row0 + ty * 8 + i;
        if (gr < n) {
            float4* p = (float4*)&Cout[(size_t)gr * 128 + tx * 8];
            p[0] = make_float4(acc[i][0], acc[i][1], acc[i][2], acc[i][3]);
            p[1] = make_float4(acc[i][4], acc[i][5], acc[i][6], acc[i][7]);
        }
    }
}

// ---------------- pull-based aggregation + fused bias/self-loop + BN stats ----------------
// one warp per node; lane l owns columns [4l, 4l+4)
__global__ __launch_bounds__(256)
void k_aggregate(const float* __restrict__ hw, const int* __restrict__ rowptr,
                 const int* __restrict__ csrc, const float* __restrict__ cw,
                 const float* __restrict__ bias, const float* __restrict__ dis,
                 float* __restrict__ agg, float* __restrict__ bsum,
                 float* __restrict__ bsumsq, int n) {
    __shared__ float ssum[128];
    __shared__ float ssq[128];
    int tid = threadIdx.x;
    if (tid < 128) { ssum[tid] = 0.0f; ssq[tid] = 0.0f; }
    __syncthreads();

    int warp = tid >> 5, lane = tid & 31;
    int node = blockIdx.x * 8 + warp;
    if (node < n) {
        const float4* hw4 = (const float4*)hw;
        float d = dis[node];
        float sn = d * d;
        float4 b = ((const float4*)bias)[lane];
        float4 v0 = hw4[(size_t)node * 32 + lane];
        float4 acc;
        acc.x = b.x + sn * v0.x;
        acc.y = b.y + sn * v0.y;
        acc.z = b.z + sn * v0.z;
        acc.w = b.w + sn * v0.w;

        int j = rowptr[node];
        int end = rowptr[node + 1];
        // unroll-4 for MLP
        for (; j + 3 < end; j += 4) {
            int s0 = __ldg(&csrc[j]);
            int s1 = __ldg(&csrc[j + 1]);
            int s2 = __ldg(&csrc[j + 2]);
            int s3 = __ldg(&csrc[j + 3]);
            float w0 = __ldg(&cw[j]);
            float w1 = __ldg(&cw[j + 1]);
            float w2 = __ldg(&cw[j + 2]);
            float w3 = __ldg(&cw[j + 3]);
            float4 a0 = hw4[(size_t)s0 * 32 + lane];
            float4 a1 = hw4[(size_t)s1 * 32 + lane];
            float4 a2 = hw4[(size_t)s2 * 32 + lane];
            float4 a3 = hw4[(size_t)s3 * 32 + lane];
            acc.x += w0 * a0.x; acc.y += w0 * a0.y; acc.z += w0 * a0.z; acc.w += w0 * a0.w;
            acc.x += w1 * a1.x; acc.y += w1 * a1.y; acc.z += w1 * a1.z; acc.w += w1 * a1.w;
            acc.x += w2 * a2.x; acc.y += w2 * a2.y; acc.z += w2 * a2.z; acc.w += w2 * a2.w;
            acc.x += w3 * a3.x; acc.y += w3 * a3.y; acc.z += w3 * a3.z; acc.w += w3 * a3.w;
        }
        for (; j < end; j++) {
            int s0 = __ldg(&csrc[j]);
            float w0 = __ldg(&cw[j]);
            float4 a0 = hw4[(size_t)s0 * 32 + lane];
            acc.x += w0 * a0.x; acc.y += w0 * a0.y; acc.z += w0 * a0.z; acc.w += w0 * a0.w;
        }
        ((float4*)agg)[(size_t)node * 32 + lane] = acc;

        // BN stats partials -> smem
        int c = lane * 4;
        atomicAdd(&ssum[c + 0], acc.x); atomicAdd(&ssq[c + 0], acc.x * acc.x);
        atomicAdd(&ssum[c + 1], acc.y); atomicAdd(&ssq[c + 1], acc.y * acc.y);
        atomicAdd(&ssum[c + 2], acc.z); atomicAdd(&ssq[c + 2], acc.z * acc.z);
        atomicAdd(&ssum[c + 3], acc.w); atomicAdd(&ssq[c + 3], acc.w * acc.w);
    }
    __syncthreads();
    if (tid < 128) {
        atomicAdd(&bsum[tid], ssum[tid]);
        atomicAdd(&bsumsq[tid], ssq[tid]);
    }
}

// ---------------- BN finalize ----------------
__global__ void k_zero_stats(float* __restrict__ sum, float* __restrict__ sumsq) {
    int c = threadIdx.x;
    if (c < H) { sum[c] = 0.0f; sumsq[c] = 0.0f; }
}

__global__ void k_bn_fin(const float* __restrict__ gamma, const float* __restrict__ beta,
                         const float* __restrict__ sum, const float* __restrict__ sumsq,
                         float* __restrict__ scale, float* __restrict__ shift, int n) {
    int c = threadIdx.x;
    if (c >= H) return;
    float inv_n = 1.0f / (float)n;
    float mean = sum[c] * inv_n;
    float var = fmaxf(sumsq[c] * inv_n - mean * mean, 0.0f);
    float inv = rsqrtf(var + EPS);
    float sc = gamma[c] * inv;
    scale[c] = sc;
    shift[c] = beta[c] - mean * sc;
}

// ---------------- head: BN3+ReLU -> FC -> ReLU -> log_softmax ----------------
__global__ __launch_bounds__(256)
void k_head(const float* __restrict__ agg, const float* __restrict__ fcW,
            const float* __restrict__ fcb, const float* __restrict__ scale,
            const float* __restrict__ shift, float* __restrict__ lsm,
            float* __restrict__ logits, int n) {
    __shared__ float Wf[128 * 40];
    __shared__ float fb[40];
    __shared__ float hs[32][129];
    __shared__ float lg[32][40];
    __shared__ float nlse[32];

    int tid = threadIdx.x;
    for (int i = tid; i < 128 * 40; i += 256) Wf[i] = fcW[i];
    if (tid < 40) fb[tid] = fcb[tid];

    int node0 = blockIdx.x * 32;
    for (int i = tid; i < 32 * 128; i += 256) {
        int r = i >> 7, c = i & 127;
        int gn = node0 + r;
        float v = 0.0f;
        if (gn < n) {
            v = agg[(size_t)gn * 128 + c];
            v = fmaxf(v * scale[c] + shift[c], 0.0f);
        }
        hs[r][c] = v;
    }
    __syncthreads();

    int nd = tid >> 3;
    int cg = (tid & 7) * 5;
    float acc[5] = {0, 0, 0, 0, 0};
    for (int k = 0; k < 128; k++) {
        float h = hs[nd][k];
#pragma unroll
        for (int j = 0; j < 5; j++) acc[j] += h * Wf[k * 40 + cg + j];
    }
#pragma unroll
    for (int j = 0; j < 5; j++) lg[nd][cg + j] = fmaxf(acc[j] + fb[cg + j], 0.0f);
    __syncthreads();

    if (tid < 32) {
        float m = -1e30f;
        for (int c = 0; c < 40; c++) m = fmaxf(m, lg[tid][c]);
        float s = 0.0f;
        for (int c = 0; c < 40; c++) s += expf(lg[tid][c] - m);
        nlse[tid] = m + logf(s);
    }
    __syncthreads();

    for (int i = tid; i < 32 * 40; i += 256) {
        int r = i / 40, c = i - r * 40;
        int gn = node0 + r;
        if (gn < n) {
            float l = lg[r][c];
            logits[(size_t)gn * 40 + c] = l;
            lsm[(size_t)gn * 40 + c] = l - nlse[r];
        }
    }
}

// ---------------- host ----------------
extern "C" void kernel_launch(void* const* d_in, const int* in_sizes, int n_in,
                              void* d_out, int out_size) {
    const float* x   = (const float*)d_in[0];
    const int*   ei  = (const int*)d_in[1];
    const float* W1  = (const float*)d_in[2];
    const float* b1  = (const float*)d_in[3];
    const float* W2  = (const float*)d_in[4];
    const float* b2  = (const float*)d_in[5];
    const float* W3  = (const float*)d_in[6];
    const float* b3  = (const float*)d_in[7];
    const float* g1  = (const float*)d_in[8];
    const float* be1 = (const float*)d_in[9];
    const float* g2  = (const float*)d_in[10];
    const float* be2 = (const float*)d_in[11];
    const float* g3  = (const float*)d_in[12];
    const float* be3 = (const float*)d_in[13];
    const float* fcW = (const float*)d_in[14];
    const float* fcb = (const float*)d_in[15];

    int n = in_sizes[0] / H;
    int e = in_sizes[1] / 2;
    const int* src = ei;
    const int* dst = ei + e;

    float *buf0, *buf1, *dis, *cwp, *sum, *sumsq, *scale, *shift, *lscr;
    int *cnt, *rowptr, *cursor, *csrc;
    cudaGetSymbolAddress((void**)&buf0, g_buf0);
    cudaGetSymbolAddress((void**)&buf1, g_buf1);
    cudaGetSymbolAddress((void**)&dis, g_dis);
    cudaGetSymbolAddress((void**)&cnt, g_cnt);
    cudaGetSymbolAddress((void**)&rowptr, g_rowptr);
    cudaGetSymbolAddress((void**)&cursor, g_cursor);
    cudaGetSymbolAddress((void**)&csrc, g_csrc);
    cudaGetSymbolAddress((void**)&cwp, g_cw);
    cudaGetSymbolAddress((void**)&sum, g_sum);
    cudaGetSymbolAddress((void**)&sumsq, g_sumsq);
    cudaGetSymbolAddress((void**)&scale, g_scale);
    cudaGetSymbolAddress((void**)&shift, g_shift);
    cudaGetSymbolAddress((void**)&lscr, g_logits_scratch);

    float* lsm = (float*)d_out;
    float* logits = (out_size >= 2 * n * CC) ? (lsm + (size_t)n * CC) : lscr;

    int nb = (n + 255) / 256;
    int ebks = (e + 255) / 256;
    int gemm_blocks = (n + 127) / 128;
    int agg_blocks = (n + 7) / 8;

    // ---- CSR build ----
    k_zero_cnt<<<nb, 256>>>(cnt, n);
    k_count<<<ebks, 256>>>(dst, cnt, e);
    k_dis<<<nb, 256>>>(cnt, dis, n);
    k_scan<<<1, 1024>>>(cnt, rowptr, cursor, n);
    k_fill<<<ebks, 256>>>(src, dst, dis, cursor, csrc, cwp, e);

    // ---- layer 1 ----
    k_gemm<<<gemm_blocks, 256>>>(x, W1, nullptr, nullptr, buf0, n);
    k_zero_stats<<<1, 128>>>(sum, sumsq);
    k_aggregate<<<agg_blocks, 256>>>(buf0, rowptr, csrc, cwp, b1, dis, buf1, sum, sumsq, n);
    k_bn_fin<<<1, 128>>>(g1, be1, sum, sumsq, scale, shift, n);

    // ---- layer 2 ----
    k_gemm<<<gemm_blocks, 256>>>(buf1, W2, scale, shift, buf0, n);
    k_zero_stats<<<1, 128>>>(sum, sumsq);
    k_aggregate<<<agg_blocks, 256>>>(buf0, rowptr, csrc, cwp, b2, dis, buf1, sum, sumsq, n);
    k_bn_fin<<<1, 128>>>(g2, be2, sum, sumsq, scale, shift, n);

    // ---- layer 3 ----
    k_gemm<<<gemm_blocks, 256>>>(buf1, W3, scale, shift, buf0, n);
    k_zero_stats<<<1, 128>>>(sum, sumsq);
    k_aggregate<<<agg_blocks, 256>>>(buf0, rowptr, csrc, cwp, b3, dis, buf1, sum, sumsq, n);
    k_bn_fin<<<1, 128>>>(g3, be3, sum, sumsq, scale, shift, n);

    // ---- head ----
    k_head<<<(n + 31) / 32, 256>>>(buf1, fcW, fcb, scale, shift, lsm, logits, n);
}

// round 4
// speedup vs baseline: 1.8114x; 1.1469x over previous
#include <cuda_runtime.h>
#include <cuda_fp16.h>
#include <math.h>

#define NN 50000
#define MAXE 1600000
#define H 128
#define CC 40
#define EPS 1e-5f

// ---------------- static device scratch ----------------
__device__ __half g_hw[NN * H];      // GEMM output in fp16 (gather source)
__device__ float g_agg[NN * H];      // aggregation output (fp32)
__device__ float g_dis[NN];
__device__ int   g_cnt[NN];
__device__ int   g_rowptr[NN + 1];
__device__ int   g_cursor[NN];
__device__ int   g_csrc[MAXE];
__device__ float g_cw[MAXE];
__device__ int   g_bsum[128];
__device__ int   g_boff[128];
__device__ float g_sum[H];
__device__ float g_sumsq[H];
__device__ float g_scale[H];
__device__ float g_shift[H];
__device__ float g_logits_scratch[NN * CC];

// ---------------- CSR build ----------------
__global__ void k_zero_cnt(int* __restrict__ cnt, int n) {
    int i = blockIdx.x * blockDim.x + threadIdx.x;
    if (i < n) cnt[i] = 0;
}

__global__ void k_count(const int* __restrict__ dst, int* __restrict__ cnt, int e) {
    int i = blockIdx.x * blockDim.x + threadIdx.x;
    if (i < e) atomicAdd(&cnt[dst[i]], 1);
}

__global__ void k_dis(const int* __restrict__ cnt, float* __restrict__ dis, int n) {
    int i = blockIdx.x * blockDim.x + threadIdx.x;
    if (i < n) dis[i] = rsqrtf((float)(cnt[i] + 1));
}

// multi-block scan, pass 1: per-block exclusive scan + block totals
__global__ __launch_bounds__(1024)
void k_scan_blk(const int* __restrict__ cnt, int* __restrict__ rowptr,
                int* __restrict__ bsum, int n) {
    __shared__ int warpsums[32];
    int tid = threadIdx.x;
    int lane = tid & 31, wid = tid >> 5;
    int i = blockIdx.x * 1024 + tid;
    int v = (i < n) ? cnt[i] : 0;
    int x = v;
#pragma unroll
    for (int o = 1; o < 32; o <<= 1) {
        int t = __shfl_up_sync(0xffffffffu, x, o);
        if (lane >= o) x += t;
    }
    if (lane == 31) warpsums[wid] = x;
    __syncthreads();
    if (wid == 0) {
        int w = warpsums[lane];
#pragma unroll
        for (int o = 1; o < 32; o <<= 1) {
            int t = __shfl_up_sync(0xffffffffu, w, o);
            if (lane >= o) w += t;
        }
        warpsums[lane] = w;
    }
    __syncthreads();
    int excl = x - v + (wid > 0 ? warpsums[wid - 1] : 0);
    if (i < n) rowptr[i] = excl;
    if (tid == 1023) bsum[blockIdx.x] = excl + v;
}

// pass 2: serial scan of block sums (<=128 blocks, trivial)
__global__ void k_scan_top(const int* __restrict__ bsum, int* __restrict__ boff, int nb) {
    if (threadIdx.x == 0) {
        int run = 0;
        for (int b = 0; b < nb; b++) { boff[b] = run; run += bsum[b]; }
    }
}

// pass 3: add block offsets, init cursor, set rowptr[n]=e
__global__ void k_scan_add(int* __restrict__ rowptr, int* __restrict__ cursor,
                           const int* __restrict__ boff, int n, int e) {
    int i = blockIdx.x * blockDim.x + threadIdx.x;
    if (i < n) {
        int v = rowptr[i] + boff[i >> 10];
        rowptr[i] = v;
        cursor[i] = v;
    }
    if (i == 0) rowptr[n] = e;
}

__global__ void k_fill(const int* __restrict__ src, const int* __restrict__ dst,
                       const float* __restrict__ dis, int* __restrict__ cursor,
                       int* __restrict__ csrc, float* __restrict__ cw, int e) {
    int i = blockIdx.x * blockDim.x + threadIdx.x;
    if (i >= e) return;
    int s = src[i], d = dst[i];
    int pos = atomicAdd(&cursor[d], 1);
    csrc[pos] = s;
    cw[pos] = __ldg(&dis[s]) * __ldg(&dis[d]);
}

// ---------------- GEMM: Ch[n,128](fp16) = f(A)[n,128] @ W[128,128] ----------------
__global__ __launch_bounds__(256)
void k_gemm(const float* __restrict__ A, const float* __restrict__ W,
            const float* __restrict__ scale, const float* __restrict__ shift,
            __half* __restrict__ Cout, int n) {
    __shared__ float As[128 * 33];
    __shared__ float Ws[32 * 128];

    int tid = threadIdx.x;
    int tx = tid & 15;
    int ty = tid >> 4;
    int row0 = blockIdx.x * 128;

    float acc[8][8];
#pragma unroll
    for (int i = 0; i < 8; i++)
#pragma unroll
        for (int j = 0; j < 8; j++) acc[i][j] = 0.0f;

    for (int k0 = 0; k0 < 128; k0 += 32) {
        for (int i = tid; i < 128 * 32; i += 256) {
            int r = i >> 5, c = i & 31;
            int gr = row0 + r;
            float v = 0.0f;
            if (gr < n) {
                v = A[(size_t)gr * 128 + k0 + c];
                if (scale) v = fmaxf(v * scale[k0 + c] + shift[k0 + c], 0.0f);
            }
            As[r * 33 + c] = v;
        }
        for (int i = tid; i < 32 * 128; i += 256) {
            int kk = i >> 7, nn = i & 127;
            Ws[i] = W[(size_t)(k0 + kk) * 128 + nn];
        }
        __syncthreads();

#pragma unroll
        for (int kk = 0; kk < 32; kk++) {
            float a[8];
#pragma unroll
            for (int i = 0; i < 8; i++) a[i] = As[(ty * 8 + i) * 33 + kk];
            float4 w0 = *(const float4*)&Ws[kk * 128 + tx * 8];
            float4 w1 = *(const float4*)&Ws[kk * 128 + tx * 8 + 4];
#pragma unroll
            for (int i = 0; i < 8; i++) {
                acc[i][0] += a[i] * w0.x;
                acc[i][1] += a[i] * w0.y;
                acc[i][2] += a[i] * w0.z;
                acc[i][3] += a[i] * w0.w;
                acc[i][4] += a[i] * w1.x;
                acc[i][5] += a[i] * w1.y;
                acc[i][6] += a[i] * w1.z;
                acc[i][7] += a[i] * w1.w;
            }
        }
        __syncthreads();
    }

#pragma unroll
    for (int i = 0; i < 8; i++) {
        int gr = row0 + ty * 8 + i;
        if (gr < n) {
            __half2 h[4];
            h[0] = __floats2half2_rn(acc[i][0], acc[i][1]);
            h[1] = __floats2half2_rn(acc[i][2], acc[i][3]);
            h[2] = __floats2half2_rn(acc[i][4], acc[i][5]);
            h[3] = __floats2half2_rn(acc[i][6], acc[i][7]);
            *(uint4*)&Cout[(size_t)gr * 128 + tx * 8] = *(uint4*)h;
        }
    }
}

// ---------------- pull aggregation (fp16 gather) + bias/self-loop + BN stats ----------------
// one warp per node; lane l owns columns [4l, 4l+4)
__global__ __launch_bounds__(256)
void k_aggregate(const __half* __restrict__ hw, const int* __restrict__ rowptr,
                 const int* __restrict__ csrc, const float* __restrict__ cw,
                 const float* __restrict__ bias, const float* __restrict__ dis,
                 float* __restrict__ agg, float* __restrict__ bsum,
                 float* __restrict__ bsumsq, int n) {
    __shared__ float ssum[128];
    __shared__ float ssq[128];
    int tid = threadIdx.x;
    if (tid < 128) { ssum[tid] = 0.0f; ssq[tid] = 0.0f; }
    __syncthreads();

    int warp = tid >> 5, lane = tid & 31;
    int node = blockIdx.x * 8 + warp;
    if (node < n) {
        const uint2* hw2 = (const uint2*)hw;   // 4 halfs per lane-slot
        float d = dis[node];
        float sn = d * d;
        float4 b = ((const float4*)bias)[lane];

        uint2 u0 = __ldg(&hw2[(size_t)node * 32 + lane]);
        __half2 s0 = *(__half2*)&u0.x, s1 = *(__half2*)&u0.y;
        float2 f0 = __half22float2(s0), f1 = __half22float2(s1);
        float4 acc;
        acc.x = b.x + sn * f0.x;
        acc.y = b.y + sn * f0.y;
        acc.z = b.z + sn * f1.x;
        acc.w = b.w + sn * f1.y;

        int j = rowptr[node];
        int end = rowptr[node + 1];
        for (; j + 3 < end; j += 4) {
            int i0 = __ldg(&csrc[j]);
            int i1 = __ldg(&csrc[j + 1]);
            int i2 = __ldg(&csrc[j + 2]);
            int i3 = __ldg(&csrc[j + 3]);
            float w0 = __ldg(&cw[j]);
            float w1 = __ldg(&cw[j + 1]);
            float w2 = __ldg(&cw[j + 2]);
            float w3 = __ldg(&cw[j + 3]);
            uint2 a0 = __ldg(&hw2[(size_t)i0 * 32 + lane]);
            uint2 a1 = __ldg(&hw2[(size_t)i1 * 32 + lane]);
            uint2 a2 = __ldg(&hw2[(size_t)i2 * 32 + lane]);
            uint2 a3 = __ldg(&hw2[(size_t)i3 * 32 + lane]);
            {
                float2 p = __half22float2(*(__half2*)&a0.x);
                float2 q = __half22float2(*(__half2*)&a0.y);
                acc.x += w0 * p.x; acc.y += w0 * p.y; acc.z += w0 * q.x; acc.w += w0 * q.y;
            }
            {
                float2 p = __half22float2(*(__half2*)&a1.x);
                float2 q = __half22float2(*(__half2*)&a1.y);
                acc.x += w1 * p.x; acc.y += w1 * p.y; acc.z += w1 * q.x; acc.w += w1 * q.y;
            }
            {
                float2 p = __half22float2(*(__half2*)&a2.x);
                float2 q = __half22float2(*(__half2*)&a2.y);
                acc.x += w2 * p.x; acc.y += w2 * p.y; acc.z += w2 * q.x; acc.w += w2 * q.y;
            }
            {
                float2 p = __half22float2(*(__half2*)&a3.x);
                float2 q = __half22float2(*(__half2*)&a3.y);
                acc.x += w3 * p.x; acc.y += w3 * p.y; acc.z += w3 * q.x; acc.w += w3 * q.y;
            }
        }
        for (; j < end; j++) {
            int i0 = __ldg(&csrc[j]);
            float w0 = __ldg(&cw[j]);
            uint2 a0 = __ldg(&hw2[(size_t)i0 * 32 + lane]);
            float2 p = __half22float2(*(__half2*)&a0.x);
            float2 q = __half22float2(*(__half2*)&a0.y);
            acc.x += w0 * p.x; acc.y += w0 * p.y; acc.z += w0 * q.x; acc.w += w0 * q.y;
        }
        ((float4*)agg)[(size_t)node * 32 + lane] = acc;

        int c = lane * 4;
        atomicAdd(&ssum[c + 0], acc.x); atomicAdd(&ssq[c + 0], acc.x * acc.x);
        atomicAdd(&ssum[c + 1], acc.y); atomicAdd(&ssq[c + 1], acc.y * acc.y);
        atomicAdd(&ssum[c + 2], acc.z); atomicAdd(&ssq[c + 2], acc.z * acc.z);
        atomicAdd(&ssum[c + 3], acc.w); atomicAdd(&ssq[c + 3], acc.w * acc.w);
    }
    __syncthreads();
    if (tid < 128) {
        atomicAdd(&bsum[tid], ssum[tid]);
        atomicAdd(&bsumsq[tid], ssq[tid]);
    }
}

// ---------------- BN finalize ----------------
__global__ void k_zero_stats(float* __restrict__ sum, float* __restrict__ sumsq) {
    int c = threadIdx.x;
    if (c < H) { sum[c] = 0.0f; sumsq[c] = 0.0f; }
}

__global__ void k_bn_fin(const float* __restrict__ gamma, const float* __restrict__ beta,
                         const float* __restrict__ sum, const float* __restrict__ sumsq,
                         float* __restrict__ scale, float* __restrict__ shift, int n) {
    int c = threadIdx.x;
    if (c >= H) return;
    float inv_n = 1.0f / (float)n;
    float mean = sum[c] * inv_n;
    float var = fmaxf(sumsq[c] * inv_n - mean * mean, 0.0f);
    float inv = rsqrtf(var + EPS);
    float sc = gamma[c] * inv;
    scale[c] = sc;
    shift[c] = beta[c] - mean * sc;
}

// ---------------- head ----------------
__global__ __launch_bounds__(256)
void k_head(const float* __restrict__ agg, const float* __restrict__ fcW,
            const float* __restrict__ fcb, const float* __restrict__ scale,
            const float* __restrict__ shift, float* __restrict__ lsm,
            float* __restrict__ logits, int n) {
    __shared__ float Wf[128 * 40];
    __shared__ float fb[40];
    __shared__ float hs[32][129];
    __shared__ float lg[32][40];
    __shared__ float nlse[32];

    int tid = threadIdx.x;
    for (int i = tid; i < 128 * 40; i += 256) Wf[i] = fcW[i];
    if (tid < 40) fb[tid] = fcb[tid];

    int node0 = blockIdx.x * 32;
    for (int i = tid; i < 32 * 128; i += 256) {
        int r = i >> 7, c = i & 127;
        int gn = node0 + r;
        float v = 0.0f;
        if (gn < n) {
            v = agg[(size_t)gn * 128 + c];
            v = fmaxf(v * scale[c] + shift[c], 0.0f);
        }
        hs[r][c] = v;
    }
    __syncthreads();

    int nd = tid >> 3;
    int cg = (tid & 7) * 5;
    float acc[5] = {0, 0, 0, 0, 0};
    for (int k = 0; k < 128; k++) {
        float h = hs[nd][k];
#pragma unroll
        for (int j = 0; j < 5; j++) acc[j] += h * Wf[k * 40 + cg + j];
    }
#pragma unroll
    for (int j = 0; j < 5; j++) lg[nd][cg + j] = fmaxf(acc[j] + fb[cg + j], 0.0f);
    __syncthreads();

    if (tid < 32) {
        float m = -1e30f;
        for (int c = 0; c < 40; c++) m = fmaxf(m, lg[tid][c]);
        float s = 0.0f;
        for (int c = 0; c < 40; c++) s += expf(lg[tid][c] - m);
        nlse[tid] = m + logf(s);
    }
    __syncthreads();

    for (int i = tid; i < 32 * 40; i += 256) {
        int r = i / 40, c = i - r * 40;
        int gn = node0 + r;
        if (gn < n) {
            float l = lg[r][c];
            logits[(size_t)gn * 40 + c] = l;
            lsm[(size_t)gn * 40 + c] = l - nlse[r];
        }
    }
}

// ---------------- host ----------------
extern "C" void kernel_launch(void* const* d_in, const int* in_sizes, int n_in,
                              void* d_out, int out_size) {
    const float* x   = (const float*)d_in[0];
    const int*   ei  = (const int*)d_in[1];
    const float* W1  = (const float*)d_in[2];
    const float* b1  = (const float*)d_in[3];
    const float* W2  = (const float*)d_in[4];
    const float* b2  = (const float*)d_in[5];
    const float* W3  = (const float*)d_in[6];
    const float* b3  = (const float*)d_in[7];
    const float* g1  = (const float*)d_in[8];
    const float* be1 = (const float*)d_in[9];
    const float* g2  = (const float*)d_in[10];
    const float* be2 = (const float*)d_in[11];
    const float* g3  = (const float*)d_in[12];
    const float* be3 = (const float*)d_in[13];
    const float* fcW = (const float*)d_in[14];
    const float* fcb = (const float*)d_in[15];

    int n = in_sizes[0] / H;
    int e = in_sizes[1] / 2;
    const int* src = ei;
    const int* dst = ei + e;

    float *agg, *dis, *cwp, *sum, *sumsq, *scale, *shift, *lscr;
    __half* hw;
    int *cnt, *rowptr, *cursor, *csrc, *bsum, *boff;
    cudaGetSymbolAddress((void**)&hw, g_hw);
    cudaGetSymbolAddress((void**)&agg, g_agg);
    cudaGetSymbolAddress((void**)&dis, g_dis);
    cudaGetSymbolAddress((void**)&cnt, g_cnt);
    cudaGetSymbolAddress((void**)&rowptr, g_rowptr);
    cudaGetSymbolAddress((void**)&cursor, g_cursor);
    cudaGetSymbolAddress((void**)&csrc, g_csrc);
    cudaGetSymbolAddress((void**)&cwp, g_cw);
    cudaGetSymbolAddress((void**)&bsum, g_bsum);
    cudaGetSymbolAddress((void**)&boff, g_boff);
    cudaGetSymbolAddress((void**)&sum, g_sum);
    cudaGetSymbolAddress((void**)&sumsq, g_sumsq);
    cudaGetSymbolAddress((void**)&scale, g_scale);
    cudaGetSymbolAddress((void**)&shift, g_shift);
    cudaGetSymbolAddress((void**)&lscr, g_logits_scratch);

    float* lsm = (float*)d_out;
    float* logits = (out_size >= 2 * n * CC) ? (lsm + (size_t)n * CC) : lscr;

    int nb = (n + 255) / 256;
    int ebks = (e + 255) / 256;
    int gemm_blocks = (n + 127) / 128;
    int agg_blocks = (n + 7) / 8;
    int scan_blocks = (n + 1023) / 1024;

    // ---- CSR build ----
    k_zero_cnt<<<nb, 256>>>(cnt, n);
    k_count<<<ebks, 256>>>(dst, cnt, e);
    k_dis<<<nb, 256>>>(cnt, dis, n);
    k_scan_blk<<<scan_blocks, 1024>>>(cnt, rowptr, bsum, n);
    k_scan_top<<<1, 32>>>(bsum, boff, scan_blocks);
    k_scan_add<<<(n + 1023) / 1024, 1024>>>(rowptr, cursor, boff, n, e);
    k_fill<<<ebks, 256>>>(src, dst, dis, cursor, csrc, cwp, e);

    // ---- layer 1 ----
    k_gemm<<<gemm_blocks, 256>>>(x, W1, nullptr, nullptr, hw, n);
    k_zero_stats<<<1, 128>>>(sum, sumsq);
    k_aggregate<<<agg_blocks, 256>>>(hw, rowptr, csrc, cwp, b1, dis, agg, sum, sumsq, n);
    k_bn_fin<<<1, 128>>>(g1, be1, sum, sumsq, scale, shift, n);

    // ---- layer 2 ----
    k_gemm<<<gemm_blocks, 256>>>(agg, W2, scale, shift, hw, n);
    k_zero_stats<<<1, 128>>>(sum, sumsq);
    k_aggregate<<<agg_blocks, 256>>>(hw, rowptr, csrc, cwp, b2, dis, agg, sum, sumsq, n);
    k_bn_fin<<<1, 128>>>(g2, be2, sum, sumsq, scale, shift, n);

    // ---- layer 3 ----
    k_gemm<<<gemm_blocks, 256>>>(agg, W3, scale, shift, hw, n);
    k_zero_stats<<<1, 128>>>(sum, sumsq);
    k_aggregate<<<agg_blocks, 256>>>(hw, rowptr, csrc, cwp, b3, dis, agg, sum, sumsq, n);
    k_bn_fin<<<1, 128>>>(g3, be3, sum, sumsq, scale, shift, n);

    // ---- head ----
    k_head<<<(n + 31) / 32, 256>>>(agg, fcW, fcb, scale, shift, lsm, logits, n);
}

// round 5
// speedup vs baseline: 2.1293x; 1.1755x over previous
#include <cuda_runtime.h>
#include <cuda_fp16.h>
#include <cuda_bf16.h>
#include <math.h>

#define NN 50000
#define MAXE 1600000
#define H 128
#define CC 40
#define EPS 1e-5f

// ---------------- static device scratch ----------------
__device__ __half g_hw[NN * H];      // GEMM output in fp16 (gather source)
__device__ float g_agg[NN * H];      // aggregation output (fp32)
__device__ float g_dis[NN];
__device__ int   g_cnt[NN];
__device__ int   g_rowptr[NN + 1];
__device__ int   g_cursor[NN];
__device__ int   g_csrc[MAXE];
__device__ float g_cw[MAXE];
__device__ int   g_bsum[128];
__device__ int   g_boff[128];
__device__ float g_sum[H];
__device__ float g_sumsq[H];
__device__ float g_scale[H];
__device__ float g_shift[H];
__device__ __nv_bfloat16 g_wthi[H * H];  // W^T hi split, [n][k]
__device__ __nv_bfloat16 g_wtlo[H * H];  // W^T lo split, [n][k]
__device__ float g_logits_scratch[NN * CC];

// ---------------- CSR build ----------------
__global__ void k_zero_cnt(int* __restrict__ cnt, int n) {
    int i = blockIdx.x * blockDim.x + threadIdx.x;
    if (i < n) cnt[i] = 0;
}

__global__ void k_count(const int* __restrict__ dst, int* __restrict__ cnt, int e) {
    int i = blockIdx.x * blockDim.x + threadIdx.x;
    if (i < e) atomicAdd(&cnt[dst[i]], 1);
}

__global__ void k_dis(const int* __restrict__ cnt, float* __restrict__ dis, int n) {
    int i = blockIdx.x * blockDim.x + threadIdx.x;
    if (i < n) dis[i] = rsqrtf((float)(cnt[i] + 1));
}

__global__ __launch_bounds__(1024)
void k_scan_blk(const int* __restrict__ cnt, int* __restrict__ rowptr,
                int* __restrict__ bsum, int n) {
    __shared__ int warpsums[32];
    int tid = threadIdx.x;
    int lane = tid & 31, wid = tid >> 5;
    int i = blockIdx.x * 1024 + tid;
    int v = (i < n) ? cnt[i] : 0;
    int x = v;
#pragma unroll
    for (int o = 1; o < 32; o <<= 1) {
        int t = __shfl_up_sync(0xffffffffu, x, o);
        if (lane >= o) x += t;
    }
    if (lane == 31) warpsums[wid] = x;
    __syncthreads();
    if (wid == 0) {
        int w = warpsums[lane];
#pragma unroll
        for (int o = 1; o < 32; o <<= 1) {
            int t = __shfl_up_sync(0xffffffffu, w, o);
            if (lane >= o) w += t;
        }
        warpsums[lane] = w;
    }
    __syncthreads();
    int excl = x - v + (wid > 0 ? warpsums[wid - 1] : 0);
    if (i < n) rowptr[i] = excl;
    if (tid == 1023) bsum[blockIdx.x] = excl + v;
}

__global__ void k_scan_top(const int* __restrict__ bsum, int* __restrict__ boff, int nb) {
    if (threadIdx.x == 0) {
        int run = 0;
        for (int b = 0; b < nb; b++) { boff[b] = run; run += bsum[b]; }
    }
}

__global__ void k_scan_add(int* __restrict__ rowptr, int* __restrict__ cursor,
                           const int* __restrict__ boff, int n, int e) {
    int i = blockIdx.x * blockDim.x + threadIdx.x;
    if (i < n) {
        int v = rowptr[i] + boff[i >> 10];
        rowptr[i] = v;
        cursor[i] = v;
    }
    if (i == 0) rowptr[n] = e;
}

__global__ void k_fill(const int* __restrict__ src, const int* __restrict__ dst,
                       const float* __restrict__ dis, int* __restrict__ cursor,
                       int* __restrict__ csrc, float* __restrict__ cw, int e) {
    int i = blockIdx.x * blockDim.x + threadIdx.x;
    if (i >= e) return;
    int s = src[i], d = dst[i];
    int pos = atomicAdd(&cursor[d], 1);
    csrc[pos] = s;
    cw[pos] = __ldg(&dis[s]) * __ldg(&dis[d]);
}

// ---------------- W split: W[k][n] fp32 -> Wt_hi/lo[n][k] bf16 ----------------
__global__ void k_wsplit(const float* __restrict__ W, __nv_bfloat16* __restrict__ wth,
                         __nv_bfloat16* __restrict__ wtl) {
    int i = blockIdx.x * blockDim.x + threadIdx.x;   // 16384
    if (i >= H * H) return;
    int k = i >> 7, nn = i & 127;
    float v = W[i];
    __nv_bfloat16 h = __float2bfloat16(v);
    float rem = v - __bfloat162float(h);
    wth[nn * H + k] = h;
    wtl[nn * H + k] = __float2bfloat16(rem);
}

// ---------------- GEMM via bf16 split MMA ----------------
// C[n,128](fp16) = f(A)[n,128] @ W ; f = identity or relu(a*scale+shift)
// 3-term: Ahi*Whi + Ahi*Wlo + Alo*Whi (fp32 accum)
__device__ __forceinline__ void mma16816(float* c, const unsigned* a, const unsigned* b) {
    asm volatile(
        "mma.sync.aligned.m16n8k16.row.col.f32.bf16.bf16.f32 "
        "{%0,%1,%2,%3}, {%4,%5,%6,%7}, {%8,%9}, {%0,%1,%2,%3};"
        : "+f"(c[0]), "+f"(c[1]), "+f"(c[2]), "+f"(c[3])
        : "r"(a[0]), "r"(a[1]), "r"(a[2]), "r"(a[3]), "r"(b[0]), "r"(b[1]));
}

#define APITCH 40   // bf16 units per row (32 data + 8 pad) -> conflict-free frag loads

__global__ __launch_bounds__(256, 2)
void k_gemm_mma(const float* __restrict__ A,
                const unsigned* __restrict__ wth,   // bf16x2 view of Wt_hi [n][k]
                const unsigned* __restrict__ wtl,
                const float* __restrict__ scale, const float* __restrict__ shift,
                __half* __restrict__ Cout, int n) {
    __shared__ __nv_bfloat16 As_hi[128 * APITCH];
    __shared__ __nv_bfloat16 As_lo[128 * APITCH];
    __shared__ __nv_bfloat16 Ws_hi[128 * APITCH];
    __shared__ __nv_bfloat16 Ws_lo[128 * APITCH];

    int tid = threadIdx.x;
    int w = tid >> 5, lane = tid & 31;
    int wm = w >> 2, wn = w & 3;        // warp tile: rows wm*64, cols wn*32
    int g = lane >> 2, tig = lane & 3;
    int row0blk = blockIdx.x * 128;

    float acc[4][4][4];
#pragma unroll
    for (int a = 0; a < 4; a++)
#pragma unroll
        for (int b = 0; b < 4; b++)
#pragma unroll
            for (int c = 0; c < 4; c++) acc[a][b][c] = 0.0f;

    for (int k0 = 0; k0 < 128; k0 += 32) {
        // A chunk: load fp32, fuse BN+ReLU, split hi/lo
        for (int i = tid; i < 128 * 32; i += 256) {
            int r = i >> 5, c = i & 31;
            int gr = row0blk + r;
            float v = 0.0f;
            if (gr < n) {
                v = A[(size_t)gr * 128 + k0 + c];
                if (scale) v = fmaxf(v * scale[k0 + c] + shift[k0 + c], 0.0f);
            }
            __nv_bfloat16 h = __float2bfloat16(v);
            As_hi[r * APITCH + c] = h;
            As_lo[r * APITCH + c] = __float2bfloat16(v - __bfloat162float(h));
        }
        // W chunk (pre-split, transposed): copy u32-wise
        for (int i = tid; i < 2048; i += 256) {
            int nn = i >> 4, kk = i & 15;   // kk = u32 index within 32-k chunk
            ((unsigned*)&Ws_hi[nn * APITCH])[kk] = wth[nn * 64 + (k0 >> 1) + kk];
            ((unsigned*)&Ws_lo[nn * APITCH])[kk] = wtl[nn * 64 + (k0 >> 1) + kk];
        }
        __syncthreads();

#pragma unroll
        for (int ks = 0; ks < 2; ks++) {
            int ca = ks * 16 + 2 * tig;
            unsigned ah[4][4], al[4][4];
#pragma unroll
            for (int mf = 0; mf < 4; mf++) {
                int r0 = (wm * 64 + mf * 16 + g) * APITCH;
                int r1 = r0 + 8 * APITCH;
                ah[mf][0] = *(const unsigned*)&As_hi[r0 + ca];
                ah[mf][1] = *(const unsigned*)&As_hi[r1 + ca];
                ah[mf][2] = *(const unsigned*)&As_hi[r0 + ca + 8];
                ah[mf][3] = *(const unsigned*)&As_hi[r1 + ca + 8];
                al[mf][0] = *(const unsigned*)&As_lo[r0 + ca];
                al[mf][1] = *(const unsigned*)&As_lo[r1 + ca];
                al[mf][2] = *(const unsigned*)&As_lo[r0 + ca + 8];
                al[mf][3] = *(const unsigned*)&As_lo[r1 + ca + 8];
            }
#pragma unroll
            for (int nf = 0; nf < 4; nf++) {
                int nb = (wn * 32 + nf * 8 + g) * APITCH;
                unsigned bh[2], bl[2];
                bh[0] = *(const unsigned*)&Ws_hi[nb + ca];
                bh[1] = *(const unsigned*)&Ws_hi[nb + ca + 8];
                bl[0] = *(const unsigned*)&Ws_lo[nb + ca];
                bl[1] = *(const unsigned*)&Ws_lo[nb + ca + 8];
#pragma unroll
                for (int mf = 0; mf < 4; mf++) {
                    mma16816(acc[mf][nf], ah[mf], bh);
                    mma16816(acc[mf][nf], ah[mf], bl);
                    mma16816(acc[mf][nf], al[mf], bh);
                }
            }
        }
        __syncthreads();
    }

    // store fp16
#pragma unroll
    for (int mf = 0; mf < 4; mf++) {
        int gr0 = row0blk + wm * 64 + mf * 16 + g;
        int gr1 = gr0 + 8;
#pragma unroll
        for (int nf = 0; nf < 4; nf++) {
            int col = wn * 32 + nf * 8 + 2 * tig;
            if (gr0 < n) {
                __half2 h = __floats2half2_rn(acc[mf][nf][0], acc[mf][nf][1]);
                *(unsigned*)&Cout[(size_t)gr0 * 128 + col] = *(unsigned*)&h;
            }
            if (gr1 < n) {
                __half2 h = __floats2half2_rn(acc[mf][nf][2], acc[mf][nf][3]);
                *(unsigned*)&Cout[(size_t)gr1 * 128 + col] = *(unsigned*)&h;
            }
        }
    }
}

// ---------------- pull aggregation (fp16 gather) + bias/self-loop + BN stats ----------------
__global__ __launch_bounds__(256)
void k_aggregate(const __half* __restrict__ hw, const int* __restrict__ rowptr,
                 const int* __restrict__ csrc, const float* __restrict__ cw,
                 const float* __restrict__ bias, const float* __restrict__ dis,
                 float* __restrict__ agg, float* __restrict__ bsum,
                 float* __restrict__ bsumsq, int n) {
    __shared__ float ssum[128];
    __shared__ float ssq[128];
    int tid = threadIdx.x;
    if (tid < 128) { ssum[tid] = 0.0f; ssq[tid] = 0.0f; }
    __syncthreads();

    int warp = tid >> 5, lane = tid & 31;
    int node = blockIdx.x * 8 + warp;
    if (node < n) {
        const uint2* hw2 = (const uint2*)hw;
        float d = dis[node];
        float sn = d * d;
        float4 b = ((const float4*)bias)[lane];

        uint2 u0 = __ldg(&hw2[(size_t)node * 32 + lane]);
        float2 f0 = __half22float2(*(__half2*)&u0.x);
        float2 f1 = __half22float2(*(__half2*)&u0.y);
        float4 acc;
        acc.x = b.x + sn * f0.x;
        acc.y = b.y + sn * f0.y;
        acc.z = b.z + sn * f1.x;
        acc.w = b.w + sn * f1.y;

        int j = rowptr[node];
        int end = rowptr[node + 1];
        for (; j + 3 < end; j += 4) {
            int i0 = __ldg(&csrc[j]);
            int i1 = __ldg(&csrc[j + 1]);
            int i2 = __ldg(&csrc[j + 2]);
            int i3 = __ldg(&csrc[j + 3]);
            float w0 = __ldg(&cw[j]);
            float w1 = __ldg(&cw[j + 1]);
            float w2 = __ldg(&cw[j + 2]);
            float w3 = __ldg(&cw[j + 3]);
            uint2 a0 = __ldg(&hw2[(size_t)i0 * 32 + lane]);
            uint2 a1 = __ldg(&hw2[(size_t)i1 * 32 + lane]);
            uint2 a2 = __ldg(&hw2[(size_t)i2 * 32 + lane]);
            uint2 a3 = __ldg(&hw2[(size_t)i3 * 32 + lane]);
            {
                float2 p = __half22float2(*(__half2*)&a0.x);
                float2 q = __half22float2(*(__half2*)&a0.y);
                acc.x += w0 * p.x; acc.y += w0 * p.y; acc.z += w0 * q.x; acc.w += w0 * q.y;
            }
            {
                float2 p = __half22float2(*(__half2*)&a1.x);
                float2 q = __half22float2(*(__half2*)&a1.y);
                acc.x += w1 * p.x; acc.y += w1 * p.y; acc.z += w1 * q.x; acc.w += w1 * q.y;
            }
            {
                float2 p = __half22float2(*(__half2*)&a2.x);
                float2 q = __half22float2(*(__half2*)&a2.y);
                acc.x += w2 * p.x; acc.y += w2 * p.y; acc.z += w2 * q.x; acc.w += w2 * q.y;
            }
            {
                float2 p = __half22float2(*(__half2*)&a3.x);
                float2 q = __half22float2(*(__half2*)&a3.y);
                acc.x += w3 * p.x; acc.y += w3 * p.y; acc.z += w3 * q.x; acc.w += w3 * q.y;
            }
        }
        for (; j < end; j++) {
            int i0 = __ldg(&csrc[j]);
            float w0 = __ldg(&cw[j]);
            uint2 a0 = __ldg(&hw2[(size_t)i0 * 32 + lane]);
            float2 p = __half22float2(*(__half2*)&a0.x);
            float2 q = __half22float2(*(__half2*)&a0.y);
            acc.x += w0 * p.x; acc.y += w0 * p.y; acc.z += w0 * q.x; acc.w += w0 * q.y;
        }
        ((float4*)agg)[(size_t)node * 32 + lane] = acc;

        int c = lane * 4;
        atomicAdd(&ssum[c + 0], acc.x); atomicAdd(&ssq[c + 0], acc.x * acc.x);
        atomicAdd(&ssum[c + 1], acc.y); atomicAdd(&ssq[c + 1], acc.y * acc.y);
        atomicAdd(&ssum[c + 2], acc.z); atomicAdd(&ssq[c + 2], acc.z * acc.z);
        atomicAdd(&ssum[c + 3], acc.w); atomicAdd(&ssq[c + 3], acc.w * acc.w);
    }
    __syncthreads();
    if (tid < 128) {
        atomicAdd(&bsum[tid], ssum[tid]);
        atomicAdd(&bsumsq[tid], ssq[tid]);
    }
}

// ---------------- BN finalize ----------------
__global__ void k_zero_stats(float* __restrict__ sum, float* __restrict__ sumsq) {
    int c = threadIdx.x;
    if (c < H) { sum[c] = 0.0f; sumsq[c] = 0.0f; }
}

__global__ void k_bn_fin(const float* __restrict__ gamma, const float* __restrict__ beta,
                         const float* __restrict__ sum, const float* __restrict__ sumsq,
                         float* __restrict__ scale, float* __restrict__ shift, int n) {
    int c = threadIdx.x;
    if (c >= H) return;
    float inv_n = 1.0f / (float)n;
    float mean = sum[c] * inv_n;
    float var = fmaxf(sumsq[c] * inv_n - mean * mean, 0.0f);
    float inv = rsqrtf(var + EPS);
    float sc = gamma[c] * inv;
    scale[c] = sc;
    shift[c] = beta[c] - mean * sc;
}

// ---------------- head ----------------
__global__ __launch_bounds__(256)
void k_head(const float* __restrict__ agg, const float* __restrict__ fcW,
            const float* __restrict__ fcb, const float* __restrict__ scale,
            const float* __restrict__ shift, float* __restrict__ lsm,
            float* __restrict__ logits, int n) {
    __shared__ float Wf[128 * 40];
    __shared__ float fb[40];
    __shared__ float hs[32][129];
    __shared__ float lg[32][40];
    __shared__ float nlse[32];

    int tid = threadIdx.x;
    for (int i = tid; i < 128 * 40; i += 256) Wf[i] = fcW[i];
    if (tid < 40) fb[tid] = fcb[tid];

    int node0 = blockIdx.x * 32;
    for (int i = tid; i < 32 * 128; i += 256) {
        int r = i >> 7, c = i & 127;
        int gn = node0 + r;
        float v = 0.0f;
        if (gn < n) {
            v = agg[(size_t)gn * 128 + c];
            v = fmaxf(v * scale[c] + shift[c], 0.0f);
        }
        hs[r][c] = v;
    }
    __syncthreads();

    int nd = tid >> 3;
    int cg = (tid & 7) * 5;
    float acc[5] = {0, 0, 0, 0, 0};
    for (int k = 0; k < 128; k++) {
        float h = hs[nd][k];
#pragma unroll
        for (int j = 0; j < 5; j++) acc[j] += h * Wf[k * 40 + cg + j];
    }
#pragma unroll
    for (int j = 0; j < 5; j++) lg[nd][cg + j] = fmaxf(acc[j] + fb[cg + j], 0.0f);
    __syncthreads();

    if (tid < 32) {
        float m = -1e30f;
        for (int c = 0; c < 40; c++) m = fmaxf(m, lg[tid][c]);
        float s = 0.0f;
        for (int c = 0; c < 40; c++) s += expf(lg[tid][c] - m);
        nlse[tid] = m + logf(s);
    }
    __syncthreads();

    for (int i = tid; i < 32 * 40; i += 256) {
        int r = i / 40, c = i - r * 40;
        int gn = node0 + r;
        if (gn < n) {
            float l = lg[r][c];
            logits[(size_t)gn * 40 + c] = l;
            lsm[(size_t)gn * 40 + c] = l - nlse[r];
        }
    }
}

// ---------------- host ----------------
extern "C" void kernel_launch(void* const* d_in, const int* in_sizes, int n_in,
                              void* d_out, int out_size) {
    const float* x   = (const float*)d_in[0];
    const int*   ei  = (const int*)d_in[1];
    const float* W1  = (const float*)d_in[2];
    const float* b1  = (const float*)d_in[3];
    const float* W2  = (const float*)d_in[4];
    const float* b2  = (const float*)d_in[5];
    const float* W3  = (const float*)d_in[6];
    const float* b3  = (const float*)d_in[7];
    const float* g1  = (const float*)d_in[8];
    const float* be1 = (const float*)d_in[9];
    const float* g2  = (const float*)d_in[10];
    const float* be2 = (const float*)d_in[11];
    const float* g3  = (const float*)d_in[12];
    const float* be3 = (const float*)d_in[13];
    const float* fcW = (const float*)d_in[14];
    const float* fcb = (const float*)d_in[15];

    int n = in_sizes[0] / H;
    int e = in_sizes[1] / 2;
    const int* src = ei;
    const int* dst = ei + e;

    float *agg, *dis, *cwp, *sum, *sumsq, *scale, *shift, *lscr;
    __half* hw;
    __nv_bfloat16 *wth, *wtl;
    int *cnt, *rowptr, *cursor, *csrc, *bsum, *boff;
    cudaGetSymbolAddress((void**)&hw, g_hw);
    cudaGetSymbolAddress((void**)&agg, g_agg);
    cudaGetSymbolAddress((void**)&dis, g_dis);
    cudaGetSymbolAddress((void**)&cnt, g_cnt);
    cudaGetSymbolAddress((void**)&rowptr, g_rowptr);
    cudaGetSymbolAddress((void**)&cursor, g_cursor);
    cudaGetSymbolAddress((void**)&csrc, g_csrc);
    cudaGetSymbolAddress((void**)&cwp, g_cw);
    cudaGetSymbolAddress((void**)&bsum, g_bsum);
    cudaGetSymbolAddress((void**)&boff, g_boff);
    cudaGetSymbolAddress((void**)&sum, g_sum);
    cudaGetSymbolAddress((void**)&sumsq, g_sumsq);
    cudaGetSymbolAddress((void**)&scale, g_scale);
    cudaGetSymbolAddress((void**)&shift, g_shift);
    cudaGetSymbolAddress((void**)&wth, g_wthi);
    cudaGetSymbolAddress((void**)&wtl, g_wtlo);
    cudaGetSymbolAddress((void**)&lscr, g_logits_scratch);

    float* lsm = (float*)d_out;
    float* logits = (out_size >= 2 * n * CC) ? (lsm + (size_t)n * CC) : lscr;

    int nb = (n + 255) / 256;
    int ebks = (e + 255) / 256;
    int gemm_blocks = (n + 127) / 128;
    int agg_blocks = (n + 7) / 8;
    int scan_blocks = (n + 1023) / 1024;
    int ws_blocks = (H * H + 255) / 256;

    // ---- CSR build ----
    k_zero_cnt<<<nb, 256>>>(cnt, n);
    k_count<<<ebks, 256>>>(dst, cnt, e);
    k_dis<<<nb, 256>>>(cnt, dis, n);
    k_scan_blk<<<scan_blocks, 1024>>>(cnt, rowptr, bsum, n);
    k_scan_top<<<1, 32>>>(bsum, boff, scan_blocks);
    k_scan_add<<<(n + 1023) / 1024, 1024>>>(rowptr, cursor, boff, n, e);
    k_fill<<<ebks, 256>>>(src, dst, dis, cursor, csrc, cwp, e);

    // ---- layer 1 ----
    k_wsplit<<<ws_blocks, 256>>>(W1, wth, wtl);
    k_gemm_mma<<<gemm_blocks, 256>>>(x, (const unsigned*)wth, (const unsigned*)wtl,
                                     nullptr, nullptr, hw, n);
    k_zero_stats<<<1, 128>>>(sum, sumsq);
    k_aggregate<<<agg_blocks, 256>>>(hw, rowptr, csrc, cwp, b1, dis, agg, sum, sumsq, n);
    k_bn_fin<<<1, 128>>>(g1, be1, sum, sumsq, scale, shift, n);

    // ---- layer 2 ----
    k_wsplit<<<ws_blocks, 256>>>(W2, wth, wtl);
    k_gemm_mma<<<gemm_blocks, 256>>>(agg, (const unsigned*)wth, (const unsigned*)wtl,
                                     scale, shift, hw, n);
    k_zero_stats<<<1, 128>>>(sum, sumsq);
    k_aggregate<<<agg_blocks, 256>>>(hw, rowptr, csrc, cwp, b2, dis, agg, sum, sumsq, n);
    k_bn_fin<<<1, 128>>>(g2, be2, sum, sumsq, scale, shift, n);

    // ---- layer 3 ----
    k_wsplit<<<ws_blocks, 256>>>(W3, wth, wtl);
    k_gemm_mma<<<gemm_blocks, 256>>>(agg, (const unsigned*)wth, (const unsigned*)wtl,
                                     scale, shift, hw, n);
    k_zero_stats<<<1, 128>>>(sum, sumsq);
    k_aggregate<<<agg_blocks, 256>>>(hw, rowptr, csrc, cwp, b3, dis, agg, sum, sumsq, n);
    k_bn_fin<<<1, 128>>>(g3, be3, sum, sumsq, scale, shift, n);

    // ---- head ----
    k_head<<<(n + 31) / 32, 256>>>(agg, fcW, fcb, scale, shift, lsm, logits, n);
}